// round 3
// baseline (speedup 1.0000x reference)
#include <cuda_runtime.h>

// ---------------------------------------------------------------------------
// GCN: h1 = relu(Agg(x*on)*in @ w1 + b1); h2 = relu(Agg(h1*on)*in @ w2 + b2)
//      h3 = relu(h2 @ wm1 + bm1); out = h3 @ wm2 + bm2
// Strategy: per-launch CSR build (histogram + scan + bucket scatter), then
// gather-only aggregation (warp per node), then tiled fp32 GEMMs with fused
// bias/relu/row-scale epilogues.
// ---------------------------------------------------------------------------

#define N_MAX 100000
#define E_MAX 3200000

__device__ int   g_deg_in[N_MAX];
__device__ int   g_deg_out[N_MAX];
__device__ int   g_row_ptr[N_MAX + 1];
__device__ int   g_cursor[N_MAX];
__device__ int   g_sorted_src[E_MAX];
__device__ float g_out_norm[N_MAX];
__device__ float g_in_norm[N_MAX];
__device__ float g_agg[(size_t)N_MAX * 128];
__device__ float g_h[(size_t)N_MAX * 128];
__device__ float g_h3[(size_t)N_MAX * 256];

// ---------------------------------------------------------------------------
__global__ void zero_deg_kernel(int n, int* deg_in, int* deg_out) {
    int i = blockIdx.x * blockDim.x + threadIdx.x;
    if (i < n) { deg_in[i] = 0; deg_out[i] = 0; }
}

__global__ void hist_kernel(int e, const int* __restrict__ src,
                            const int* __restrict__ dst,
                            int* deg_in, int* deg_out) {
    int i = blockIdx.x * blockDim.x + threadIdx.x;
    if (i < e) {
        atomicAdd(&deg_out[src[i]], 1);
        atomicAdd(&deg_in[dst[i]], 1);
    }
}

// Single-block exclusive scan over n entries (chunked, shfl-based).
__global__ void scan_kernel(int n, const int* __restrict__ deg, int* __restrict__ row_ptr) {
    __shared__ int wsum[32];
    __shared__ int s_carry;
    const int tid = threadIdx.x;
    const int lane = tid & 31;
    const int wid = tid >> 5;
    if (tid == 0) s_carry = 0;
    __syncthreads();
    for (int base = 0; base < n; base += 1024) {
        int idx = base + tid;
        int v = (idx < n) ? deg[idx] : 0;
        // warp inclusive scan
        int x = v;
        #pragma unroll
        for (int o = 1; o < 32; o <<= 1) {
            int t = __shfl_up_sync(0xffffffffu, x, o);
            if (lane >= o) x += t;
        }
        if (lane == 31) wsum[wid] = x;
        __syncthreads();
        if (wid == 0) {
            int y = wsum[lane];
            #pragma unroll
            for (int o = 1; o < 32; o <<= 1) {
                int t = __shfl_up_sync(0xffffffffu, y, o);
                if (lane >= o) y += t;
            }
            wsum[lane] = y;
        }
        __syncthreads();
        int wofs = (wid > 0) ? wsum[wid - 1] : 0;
        int incl = x + wofs;
        int carry = s_carry;
        if (idx < n) row_ptr[idx] = carry + incl - v;  // exclusive
        __syncthreads();
        if (tid == 1023) s_carry = carry + wsum[31];
        __syncthreads();
    }
    if (threadIdx.x == 0) row_ptr[n] = s_carry;
}

__global__ void finalize_kernel(int n, const int* __restrict__ deg_out,
                                const int* __restrict__ deg_in,
                                const int* __restrict__ row_ptr,
                                float* out_norm, float* in_norm, int* cursor) {
    int i = blockIdx.x * blockDim.x + threadIdx.x;
    if (i < n) {
        out_norm[i] = rsqrtf((float)max(deg_out[i], 1));
        in_norm[i]  = rsqrtf((float)max(deg_in[i], 1));
        cursor[i]   = row_ptr[i];
    }
}

__global__ void scatter_kernel(int e, const int* __restrict__ src,
                               const int* __restrict__ dst,
                               int* cursor, int* __restrict__ sorted_src) {
    int i = blockIdx.x * blockDim.x + threadIdx.x;
    if (i < e) {
        int d = dst[i];
        int pos = atomicAdd(&cursor[d], 1);
        sorted_src[pos] = src[i];
    }
}

// ---------------------------------------------------------------------------
// Aggregation: one warp per node. Lane l owns feature columns [4l, 4l+4).
// acc = sum over in-edges of feat[src] (optionally * out_norm[src]),
// stored as acc * in_norm[node].
template <bool SCALE_SRC>
__global__ void agg_kernel(int n, const float* __restrict__ feat,
                           const int* __restrict__ row_ptr,
                           const int* __restrict__ srcs,
                           const float* __restrict__ onorm,
                           const float* __restrict__ inorm,
                           float* __restrict__ out) {
    int warp = (blockIdx.x * blockDim.x + threadIdx.x) >> 5;
    if (warp >= n) return;
    const int lane = threadIdx.x & 31;
    const int beg = row_ptr[warp];
    const int end = row_ptr[warp + 1];
    float4 acc = make_float4(0.f, 0.f, 0.f, 0.f);
    for (int i = beg; i < end; i += 32) {
        int cnt = min(32, end - i);
        int s = 0;
        float w = 0.f;
        if (lane < cnt) {
            s = __ldg(srcs + i + lane);
            if (SCALE_SRC) w = __ldg(onorm + s);
        }
        for (int j = 0; j < cnt; j++) {
            int sj = __shfl_sync(0xffffffffu, s, j);
            float4 v = *reinterpret_cast<const float4*>(feat + (size_t)sj * 128 + lane * 4);
            float wj = SCALE_SRC ? __shfl_sync(0xffffffffu, w, j) : 1.f;
            acc.x += v.x * wj;
            acc.y += v.y * wj;
            acc.z += v.z * wj;
            acc.w += v.w * wj;
        }
    }
    float iw = inorm[warp];
    float4 o = make_float4(acc.x * iw, acc.y * iw, acc.z * iw, acc.w * iw);
    *reinterpret_cast<float4*>(out + (size_t)warp * 128 + lane * 4) = o;
}

// ---------------------------------------------------------------------------
// Tiled fp32 GEMM: C[M x ldn] (cols [nBase, nBase+BN)) = act(A[M x K] @ W[K x ldn] + bias)
// optional per-row post-scale (for folding out_norm into next layer's input).
// BM=128, BN=64, BK=16, TM=8, TN=4, 256 threads.
template <int BM, int BN, int BK, int TM, int TN, bool RELU, bool PSCALE>
__global__ void gemm_kernel(int M, int K, int ldn,
                            const float* __restrict__ A,
                            const float* __restrict__ W,
                            const float* __restrict__ bias,
                            const float* __restrict__ pscale,
                            float* __restrict__ C) {
    constexpr int ASTRIDE = BM + 4;  // pad to kill bank conflicts on transpose store
    __shared__ float As[BK * ASTRIDE];
    __shared__ float Bs[BK * BN];

    const int tid = threadIdx.x;
    const int rowBase = blockIdx.x * BM;
    const int nBase = blockIdx.y * BN;

    const int tr = tid / (BN / TN);        // 0..15
    const int tc = tid % (BN / TN);        // 0..15
    const int aRow = tid >> 2;             // 0..63  (BK/4 = 4 float4 per A row)
    const int aCol = (tid & 3) * 4;
    const int bRow = tid / (BN / 4);       // 0..15
    const int bCol = (tid % (BN / 4)) * 4;

    float acc[TM][TN];
    #pragma unroll
    for (int i = 0; i < TM; i++)
        #pragma unroll
        for (int j = 0; j < TN; j++) acc[i][j] = 0.f;

    for (int kb = 0; kb < K; kb += BK) {
        // Load + transpose A tile
        #pragma unroll
        for (int r0 = 0; r0 < BM; r0 += 64) {
            int r = aRow + r0;
            int grow = rowBase + r;
            float4 v = make_float4(0.f, 0.f, 0.f, 0.f);
            if (grow < M)
                v = *reinterpret_cast<const float4*>(A + (size_t)grow * K + kb + aCol);
            As[(aCol + 0) * ASTRIDE + r] = v.x;
            As[(aCol + 1) * ASTRIDE + r] = v.y;
            As[(aCol + 2) * ASTRIDE + r] = v.z;
            As[(aCol + 3) * ASTRIDE + r] = v.w;
        }
        // Load B tile (one float4 per thread: BK*BN/4 == 256)
        {
            float4 v = *reinterpret_cast<const float4*>(
                W + (size_t)(kb + bRow) * ldn + nBase + bCol);
            *reinterpret_cast<float4*>(&Bs[bRow * BN + bCol]) = v;
        }
        __syncthreads();
        #pragma unroll
        for (int k = 0; k < BK; k++) {
            float a[TM], b[TN];
            #pragma unroll
            for (int i = 0; i < TM; i++) a[i] = As[k * ASTRIDE + tr * TM + i];
            #pragma unroll
            for (int j = 0; j < TN; j++) b[j] = Bs[k * BN + tc * TN + j];
            #pragma unroll
            for (int i = 0; i < TM; i++)
                #pragma unroll
                for (int j = 0; j < TN; j++) acc[i][j] += a[i] * b[j];
        }
        __syncthreads();
    }

    float bv[TN];
    #pragma unroll
    for (int j = 0; j < TN; j++) bv[j] = bias[nBase + tc * TN + j];

    #pragma unroll
    for (int i = 0; i < TM; i++) {
        int grow = rowBase + tr * TM + i;
        if (grow >= M) continue;
        float sc = PSCALE ? pscale[grow] : 1.f;
        float4 o;
        o.x = acc[i][0] + bv[0];
        o.y = acc[i][1] + bv[1];
        o.z = acc[i][2] + bv[2];
        o.w = acc[i][3] + bv[3];
        if (RELU) {
            o.x = fmaxf(o.x, 0.f);
            o.y = fmaxf(o.y, 0.f);
            o.z = fmaxf(o.z, 0.f);
            o.w = fmaxf(o.w, 0.f);
        }
        o.x *= sc; o.y *= sc; o.z *= sc; o.w *= sc;
        *reinterpret_cast<float4*>(C + (size_t)grow * ldn + nBase + tc * TN) = o;
    }
}

// ---------------------------------------------------------------------------
extern "C" void kernel_launch(void* const* d_in, const int* in_sizes, int n_in,
                              void* d_out, int out_size) {
    const float* x   = (const float*)d_in[0];
    const int*   src = (const int*)d_in[1];
    const int*   dst = (const int*)d_in[2];
    const float* w1  = (const float*)d_in[3];
    const float* b1  = (const float*)d_in[4];
    const float* w2  = (const float*)d_in[5];
    const float* b2  = (const float*)d_in[6];
    const float* wm1 = (const float*)d_in[7];
    const float* bm1 = (const float*)d_in[8];
    const float* wm2 = (const float*)d_in[9];
    const float* bm2 = (const float*)d_in[10];

    const int n = in_sizes[0] / 128;
    const int e = in_sizes[1];

    int *deg_in, *deg_out, *row_ptr, *cursor, *sorted_src;
    float *onorm, *inorm, *agg, *h, *h3;
    cudaGetSymbolAddress((void**)&deg_in, g_deg_in);
    cudaGetSymbolAddress((void**)&deg_out, g_deg_out);
    cudaGetSymbolAddress((void**)&row_ptr, g_row_ptr);
    cudaGetSymbolAddress((void**)&cursor, g_cursor);
    cudaGetSymbolAddress((void**)&sorted_src, g_sorted_src);
    cudaGetSymbolAddress((void**)&onorm, g_out_norm);
    cudaGetSymbolAddress((void**)&inorm, g_in_norm);
    cudaGetSymbolAddress((void**)&agg, g_agg);
    cudaGetSymbolAddress((void**)&h, g_h);
    cudaGetSymbolAddress((void**)&h3, g_h3);

    const int nb = (n + 255) / 256;
    const int eb = (e + 255) / 256;

    // --- CSR build ---
    zero_deg_kernel<<<nb, 256>>>(n, deg_in, deg_out);
    hist_kernel<<<eb, 256>>>(e, src, dst, deg_in, deg_out);
    scan_kernel<<<1, 1024>>>(n, deg_in, row_ptr);
    finalize_kernel<<<nb, 256>>>(n, deg_out, deg_in, row_ptr, onorm, inorm, cursor);
    scatter_kernel<<<eb, 256>>>(e, src, dst, cursor, sorted_src);

    const int aggBlocks = (n + 7) / 8;  // 8 warps/block, warp per node
    const dim3 g2((n + 127) / 128, 2);
    const dim3 g4((n + 127) / 128, 4);
    const dim3 g1((n + 127) / 128, 1);

    // --- conv1: agg(x * out_norm) * in_norm @ w1 + b1, relu, * out_norm ---
    agg_kernel<true><<<aggBlocks, 256>>>(n, x, row_ptr, sorted_src, onorm, inorm, agg);
    gemm_kernel<128, 64, 16, 8, 4, true, true>
        <<<g2, 256>>>(n, 128, 128, agg, w1, b1, onorm, h);  // h = hs1 = relu(...)*out_norm

    // --- conv2: agg(hs1) * in_norm @ w2 + b2, relu ---
    agg_kernel<false><<<aggBlocks, 256>>>(n, h, row_ptr, sorted_src, onorm, inorm, agg);
    gemm_kernel<128, 64, 16, 8, 4, true, false>
        <<<g2, 256>>>(n, 128, 128, agg, w2, b2, nullptr, h);  // h = h2

    // --- MLP ---
    gemm_kernel<128, 64, 16, 8, 4, true, false>
        <<<g4, 256>>>(n, 128, 256, h, wm1, bm1, nullptr, h3);  // h3 = relu(h2@wm1+bm1)
    gemm_kernel<128, 64, 16, 8, 4, false, false>
        <<<g1, 256>>>(n, 256, 64, h3, wm2, bm2, nullptr, (float*)d_out);
}

// round 4
// speedup vs baseline: 2.1212x; 2.1212x over previous
#include <cuda_runtime.h>
#include <cstdint>

// ---------------------------------------------------------------------------
// GCN: h1 = relu(Agg(x*on)*in @ w1 + b1); h2 = relu(Agg(h1*on)*in @ w2 + b2)
//      h3 = relu(h2 @ wm1 + bm1); out = h3 @ wm2 + bm2
// CSR build (histogram+scan+bucket scatter) -> gather-only aggregation ->
// tf32 tensor-core GEMMs (mma.sync m16n8k8) with fused bias/relu/row-scale.
// ---------------------------------------------------------------------------

#define N_MAX 100000
#define E_MAX 3200000

__device__ int   g_deg_in[N_MAX];
__device__ int   g_deg_out[N_MAX];
__device__ int   g_row_ptr[N_MAX + 1];
__device__ int   g_cursor[N_MAX];
__device__ int   g_sorted_src[E_MAX];
__device__ float g_out_norm[N_MAX];
__device__ float g_in_norm[N_MAX];
__device__ float g_agg[(size_t)N_MAX * 128];
__device__ float g_h[(size_t)N_MAX * 128];
__device__ float g_h3[(size_t)N_MAX * 256];

// ---------------------------------------------------------------------------
__global__ void zero_deg_kernel(int n, int* deg_in, int* deg_out) {
    int i = blockIdx.x * blockDim.x + threadIdx.x;
    if (i < n) { deg_in[i] = 0; deg_out[i] = 0; }
}

__global__ void hist_kernel(int e, const int* __restrict__ src,
                            const int* __restrict__ dst,
                            int* deg_in, int* deg_out) {
    int i = blockIdx.x * blockDim.x + threadIdx.x;
    if (i < e) {
        atomicAdd(&deg_out[src[i]], 1);
        atomicAdd(&deg_in[dst[i]], 1);
    }
}

// Single-block exclusive scan over n entries (chunked, shfl-based).
__global__ void scan_kernel(int n, const int* __restrict__ deg, int* __restrict__ row_ptr) {
    __shared__ int wsum[32];
    __shared__ int s_carry;
    const int tid = threadIdx.x;
    const int lane = tid & 31;
    const int wid = tid >> 5;
    if (tid == 0) s_carry = 0;
    __syncthreads();
    for (int base = 0; base < n; base += 1024) {
        int idx = base + tid;
        int v = (idx < n) ? deg[idx] : 0;
        int x = v;
        #pragma unroll
        for (int o = 1; o < 32; o <<= 1) {
            int t = __shfl_up_sync(0xffffffffu, x, o);
            if (lane >= o) x += t;
        }
        if (lane == 31) wsum[wid] = x;
        __syncthreads();
        if (wid == 0) {
            int y = wsum[lane];
            #pragma unroll
            for (int o = 1; o < 32; o <<= 1) {
                int t = __shfl_up_sync(0xffffffffu, y, o);
                if (lane >= o) y += t;
            }
            wsum[lane] = y;
        }
        __syncthreads();
        int wofs = (wid > 0) ? wsum[wid - 1] : 0;
        int incl = x + wofs;
        int carry = s_carry;
        if (idx < n) row_ptr[idx] = carry + incl - v;  // exclusive
        __syncthreads();
        if (tid == 1023) s_carry = carry + wsum[31];
        __syncthreads();
    }
    if (threadIdx.x == 0) row_ptr[n] = s_carry;
}

__global__ void finalize_kernel(int n, const int* __restrict__ deg_out,
                                const int* __restrict__ deg_in,
                                const int* __restrict__ row_ptr,
                                float* out_norm, float* in_norm, int* cursor) {
    int i = blockIdx.x * blockDim.x + threadIdx.x;
    if (i < n) {
        out_norm[i] = rsqrtf((float)max(deg_out[i], 1));
        in_norm[i]  = rsqrtf((float)max(deg_in[i], 1));
        cursor[i]   = row_ptr[i];
    }
}

__global__ void scatter_kernel(int e, const int* __restrict__ src,
                               const int* __restrict__ dst,
                               int* cursor, int* __restrict__ sorted_src) {
    int i = blockIdx.x * blockDim.x + threadIdx.x;
    if (i < e) {
        int d = dst[i];
        int pos = atomicAdd(&cursor[d], 1);
        sorted_src[pos] = src[i];
    }
}

// ---------------------------------------------------------------------------
// Aggregation: one warp per node. Lane l owns feature columns [4l, 4l+4).
template <bool SCALE_SRC>
__global__ void agg_kernel(int n, const float* __restrict__ feat,
                           const int* __restrict__ row_ptr,
                           const int* __restrict__ srcs,
                           const float* __restrict__ onorm,
                           const float* __restrict__ inorm,
                           float* __restrict__ out) {
    int warp = (blockIdx.x * blockDim.x + threadIdx.x) >> 5;
    if (warp >= n) return;
    const int lane = threadIdx.x & 31;
    const int beg = row_ptr[warp];
    const int end = row_ptr[warp + 1];
    float4 acc = make_float4(0.f, 0.f, 0.f, 0.f);
    for (int i = beg; i < end; i += 32) {
        int cnt = min(32, end - i);
        int s = 0;
        float w = 0.f;
        if (lane < cnt) {
            s = __ldg(srcs + i + lane);
            if (SCALE_SRC) w = __ldg(onorm + s);
        }
        for (int j = 0; j < cnt; j++) {
            int sj = __shfl_sync(0xffffffffu, s, j);
            float4 v = *reinterpret_cast<const float4*>(feat + (size_t)sj * 128 + lane * 4);
            float wj = SCALE_SRC ? __shfl_sync(0xffffffffu, w, j) : 1.f;
            acc.x += v.x * wj;
            acc.y += v.y * wj;
            acc.z += v.z * wj;
            acc.w += v.w * wj;
        }
    }
    float iw = inorm[warp];
    float4 o = make_float4(acc.x * iw, acc.y * iw, acc.z * iw, acc.w * iw);
    *reinterpret_cast<float4*>(out + (size_t)warp * 128 + lane * 4) = o;
}

// ---------------------------------------------------------------------------
// tf32 tensor-core GEMM via mma.sync.m16n8k8.
// Block tile 128x64x32, 256 threads = 8 warps laid out 4(M) x 2(N),
// warp tile 32x32 = 2 mTiles x 4 nTiles of m16n8.
// A row-major [M x K], W row-major [K x ldn] (cols [nBase, nBase+64)).
// Epilogue: +bias, optional relu, optional per-row scale.
// ---------------------------------------------------------------------------
__device__ __forceinline__ uint32_t f2tf32(float x) {
    uint32_t r;
    asm("cvt.rna.tf32.f32 %0, %1;" : "=r"(r) : "f"(x));
    return r;
}

__device__ __forceinline__ void mma_tf32(float c[4], uint32_t a0, uint32_t a1,
                                         uint32_t a2, uint32_t a3,
                                         uint32_t b0, uint32_t b1) {
    asm volatile(
        "mma.sync.aligned.m16n8k8.row.col.f32.tf32.tf32.f32 "
        "{%0,%1,%2,%3}, {%4,%5,%6,%7}, {%8,%9}, {%0,%1,%2,%3};\n"
        : "+f"(c[0]), "+f"(c[1]), "+f"(c[2]), "+f"(c[3])
        : "r"(a0), "r"(a1), "r"(a2), "r"(a3), "r"(b0), "r"(b1));
}

template <bool RELU, bool PSCALE>
__global__ __launch_bounds__(256) void gemm_tf32_kernel(
        int M, int K, int ldn,
        const float* __restrict__ A,
        const float* __restrict__ W,
        const float* __restrict__ bias,
        const float* __restrict__ pscale,
        float* __restrict__ C) {
    constexpr int BM = 128, BN = 64, BK = 32;
    constexpr int ASTR = BK + 4;   // 36: 4B-word stride, conflict-free frag loads
    constexpr int WSTR = BN + 4;   // 68
    __shared__ uint32_t As[BM * ASTR];
    __shared__ uint32_t Ws[BK * WSTR];

    const int tid = threadIdx.x;
    const int lane = tid & 31;
    const int wid = tid >> 5;
    const int g = lane >> 2;       // groupID 0..7
    const int tig = lane & 3;      // 0..3
    const int warpM = (wid & 3) * 32;
    const int warpN = (wid >> 2) * 32;
    const int rowBase = blockIdx.x * BM;
    const int nBase = blockIdx.y * BN;

    // staging registers for double-buffered global->smem
    float4 ra[4];
    float4 rw[2];

    // per-thread load coordinates
    const int aRow0 = tid >> 1;          // with id = tid + i*256: row = id/8? recompute below
    (void)aRow0;

    auto loadA = [&](int kb) {
        #pragma unroll
        for (int i = 0; i < 4; i++) {
            int id = tid + i * 256;        // 0..1023
            int row = id >> 3;             // 0..127
            int c4 = (id & 7) * 4;         // 0..28
            int grow = rowBase + row;
            if (grow < M)
                ra[i] = *reinterpret_cast<const float4*>(A + (size_t)grow * K + kb + c4);
            else
                ra[i] = make_float4(0.f, 0.f, 0.f, 0.f);
        }
    };
    auto loadW = [&](int kb) {
        #pragma unroll
        for (int i = 0; i < 2; i++) {
            int id = tid + i * 256;        // 0..511
            int row = id >> 4;             // 0..31
            int c4 = (id & 15) * 4;        // 0..60
            rw[i] = *reinterpret_cast<const float4*>(W + (size_t)(kb + row) * ldn + nBase + c4);
        }
    };
    auto storeA = [&]() {
        #pragma unroll
        for (int i = 0; i < 4; i++) {
            int id = tid + i * 256;
            int row = id >> 3;
            int c4 = (id & 7) * 4;
            uint32_t* p = &As[row * ASTR + c4];
            p[0] = f2tf32(ra[i].x);
            p[1] = f2tf32(ra[i].y);
            p[2] = f2tf32(ra[i].z);
            p[3] = f2tf32(ra[i].w);
        }
    };
    auto storeW = [&]() {
        #pragma unroll
        for (int i = 0; i < 2; i++) {
            int id = tid + i * 256;
            int row = id >> 4;
            int c4 = (id & 15) * 4;
            uint32_t* p = &Ws[row * WSTR + c4];
            p[0] = f2tf32(rw[i].x);
            p[1] = f2tf32(rw[i].y);
            p[2] = f2tf32(rw[i].z);
            p[3] = f2tf32(rw[i].w);
        }
    };

    float acc[2][4][4];
    #pragma unroll
    for (int m = 0; m < 2; m++)
        #pragma unroll
        for (int n = 0; n < 4; n++)
            #pragma unroll
            for (int q = 0; q < 4; q++) acc[m][n][q] = 0.f;

    loadA(0);
    loadW(0);

    for (int kb = 0; kb < K; kb += BK) {
        storeA();
        storeW();
        __syncthreads();
        if (kb + BK < K) { loadA(kb + BK); loadW(kb + BK); }

        #pragma unroll
        for (int ks = 0; ks < BK; ks += 8) {
            uint32_t af[2][4];
            #pragma unroll
            for (int m = 0; m < 2; m++) {
                int r0 = warpM + m * 16 + g;
                int r1 = r0 + 8;
                af[m][0] = As[r0 * ASTR + ks + tig];
                af[m][1] = As[r1 * ASTR + ks + tig];
                af[m][2] = As[r0 * ASTR + ks + tig + 4];
                af[m][3] = As[r1 * ASTR + ks + tig + 4];
            }
            uint32_t bf[4][2];
            #pragma unroll
            for (int n = 0; n < 4; n++) {
                int cn = warpN + n * 8 + g;
                bf[n][0] = Ws[(ks + tig) * WSTR + cn];
                bf[n][1] = Ws[(ks + tig + 4) * WSTR + cn];
            }
            #pragma unroll
            for (int m = 0; m < 2; m++)
                #pragma unroll
                for (int n = 0; n < 4; n++)
                    mma_tf32(acc[m][n], af[m][0], af[m][1], af[m][2], af[m][3],
                             bf[n][0], bf[n][1]);
        }
        __syncthreads();
    }

    // Epilogue: C[row][col] with row = rowBase+warpM+m*16+g(+8),
    //           col = nBase+warpN+n*8+tig*2 (+1)
    #pragma unroll
    for (int n = 0; n < 4; n++) {
        int col = nBase + warpN + n * 8 + tig * 2;
        float bv0 = bias[col];
        float bv1 = bias[col + 1];
        #pragma unroll
        for (int m = 0; m < 2; m++) {
            int row0 = rowBase + warpM + m * 16 + g;
            int row1 = row0 + 8;
            if (row0 < M) {
                float sc = PSCALE ? pscale[row0] : 1.f;
                float o0 = acc[m][n][0] + bv0;
                float o1 = acc[m][n][1] + bv1;
                if (RELU) { o0 = fmaxf(o0, 0.f); o1 = fmaxf(o1, 0.f); }
                float2 o = make_float2(o0 * sc, o1 * sc);
                *reinterpret_cast<float2*>(C + (size_t)row0 * ldn + col) = o;
            }
            if (row1 < M) {
                float sc = PSCALE ? pscale[row1] : 1.f;
                float o2 = acc[m][n][2] + bv0;
                float o3 = acc[m][n][3] + bv1;
                if (RELU) { o2 = fmaxf(o2, 0.f); o3 = fmaxf(o3, 0.f); }
                float2 o = make_float2(o2 * sc, o3 * sc);
                *reinterpret_cast<float2*>(C + (size_t)row1 * ldn + col) = o;
            }
        }
    }
}

// ---------------------------------------------------------------------------
extern "C" void kernel_launch(void* const* d_in, const int* in_sizes, int n_in,
                              void* d_out, int out_size) {
    const float* x   = (const float*)d_in[0];
    const int*   src = (const int*)d_in[1];
    const int*   dst = (const int*)d_in[2];
    const float* w1  = (const float*)d_in[3];
    const float* b1  = (const float*)d_in[4];
    const float* w2  = (const float*)d_in[5];
    const float* b2  = (const float*)d_in[6];
    const float* wm1 = (const float*)d_in[7];
    const float* bm1 = (const float*)d_in[8];
    const float* wm2 = (const float*)d_in[9];
    const float* bm2 = (const float*)d_in[10];

    const int n = in_sizes[0] / 128;
    const int e = in_sizes[1];

    int *deg_in, *deg_out, *row_ptr, *cursor, *sorted_src;
    float *onorm, *inorm, *agg, *h, *h3;
    cudaGetSymbolAddress((void**)&deg_in, g_deg_in);
    cudaGetSymbolAddress((void**)&deg_out, g_deg_out);
    cudaGetSymbolAddress((void**)&row_ptr, g_row_ptr);
    cudaGetSymbolAddress((void**)&cursor, g_cursor);
    cudaGetSymbolAddress((void**)&sorted_src, g_sorted_src);
    cudaGetSymbolAddress((void**)&onorm, g_out_norm);
    cudaGetSymbolAddress((void**)&inorm, g_in_norm);
    cudaGetSymbolAddress((void**)&agg, g_agg);
    cudaGetSymbolAddress((void**)&h, g_h);
    cudaGetSymbolAddress((void**)&h3, g_h3);

    const int nb = (n + 255) / 256;
    const int eb = (e + 255) / 256;

    // --- CSR build ---
    zero_deg_kernel<<<nb, 256>>>(n, deg_in, deg_out);
    hist_kernel<<<eb, 256>>>(e, src, dst, deg_in, deg_out);
    scan_kernel<<<1, 1024>>>(n, deg_in, row_ptr);
    finalize_kernel<<<nb, 256>>>(n, deg_out, deg_in, row_ptr, onorm, inorm, cursor);
    scatter_kernel<<<eb, 256>>>(e, src, dst, cursor, sorted_src);

    const int aggBlocks = (n + 7) / 8;  // 8 warps/block, warp per node
    const dim3 g2((n + 127) / 128, 2);
    const dim3 g4((n + 127) / 128, 4);
    const dim3 g1((n + 127) / 128, 1);

    // --- conv1: agg(x * out_norm) * in_norm @ w1 + b1, relu, * out_norm ---
    agg_kernel<true><<<aggBlocks, 256>>>(n, x, row_ptr, sorted_src, onorm, inorm, agg);
    gemm_tf32_kernel<true, true><<<g2, 256>>>(n, 128, 128, agg, w1, b1, onorm, h);

    // --- conv2: agg(hs1) * in_norm @ w2 + b2, relu ---
    agg_kernel<false><<<aggBlocks, 256>>>(n, h, row_ptr, sorted_src, onorm, inorm, agg);
    gemm_tf32_kernel<true, false><<<g2, 256>>>(n, 128, 128, agg, w2, b2, nullptr, h);

    // --- MLP ---
    gemm_tf32_kernel<true, false><<<g4, 256>>>(n, 128, 256, h, wm1, bm1, nullptr, h3);
    gemm_tf32_kernel<false, false><<<g1, 256>>>(n, 256, 64, h3, wm2, bm2, nullptr, (float*)d_out);
}